// round 9
// baseline (speedup 1.0000x reference)
#include <cuda_runtime.h>
#include <cstdint>

// 9-DoF alignment, persistent warps + cp.async staging.
// Each warp grid-strides over batches; chunk pipeline (3-slot smem ring,
// 2 chunks ahead) is CONTINUOUS across batch boundaries, so the next batch's
// loads are in flight while this batch's reduce/Newton epilogue runs.
//
// Chunk = 128 points (1536B x + 1536B y). 8 chunks per batch.
// Readback: 3 scalar LDS.32 per point, bank-conflict-free (gcd(3,32)=1).
// No __syncthreads anywhere; only cp.async.wait_group + __syncwarp.

#define SLOT_BYTES   3072
#define WARP_SMEM    (3 * SLOT_BYTES)   // 9216B ring per warp
#define CTA_SMEM     (8 * WARP_SMEM)    // 73728B per CTA (8 warps)

__device__ __forceinline__ void cp_async16(uint32_t saddr, const void* gaddr) {
    asm volatile("cp.async.cg.shared.global [%0], [%1], 16;\n"
                 :: "r"(saddr), "l"(gaddr));
}
__device__ __forceinline__ void cp_commit() {
    asm volatile("cp.async.commit_group;\n");
}
template <int N>
__device__ __forceinline__ void cp_wait() {
    asm volatile("cp.async.wait_group %0;\n" :: "n"(N));
}

__global__ __launch_bounds__(256, 3)
void align9dof_kernel(const float* __restrict__ x,
                      const float* __restrict__ mu_x,
                      const float* __restrict__ y,
                      const float* __restrict__ mu_y,
                      float* __restrict__ out,
                      int B)
{
    extern __shared__ char smem_dyn[];

    const int warp = threadIdx.x >> 5;
    const int lane = threadIdx.x & 31;
    const int gw   = blockIdx.x * 8 + warp;   // global warp id
    const int ws   = gridDim.x * 8;           // warp stride
    if (gw >= B) return;

    const int nb   = (B - 1 - gw) / ws + 1;   // batches this warp owns
    const int qtot = nb * 8;                  // total chunks in this warp's stream

    char* wbase = smem_dyn + warp * WARP_SMEM;
    const uint32_t sbase = (uint32_t)__cvta_generic_to_shared(wbase);

    // Issue chunk q of the stream: batch gw + (q>>3)*ws, chunk (q&7)
    auto issue_chunk = [&](int q) {
        const size_t bq = (size_t)gw + (size_t)(q >> 3) * ws;
        const char* gx = (const char*)(x + bq * 3072) + (q & 7) * 1536 + lane * 16;
        const char* gy = (const char*)(y + bq * 3072) + (q & 7) * 1536 + lane * 16;
        const uint32_t s = sbase + (q % 3) * SLOT_BYTES + lane * 16;
#pragma unroll
        for (int k = 0; k < 3; k++) {
            cp_async16(s + k * 512,        gx + k * 512);
            cp_async16(s + 1536 + k * 512, gy + k * 512);
        }
        cp_commit();
    };

    // Prologue: two chunks in flight (qtot >= 8 always)
    issue_chunk(0);
    issue_chunk(1);

    float mx0 = 0.f, mx1 = 0.f, mx2 = 0.f, my0 = 0.f, my1 = 0.f, my2 = 0.f;

    float v[11];  // c00..c22, sxx, syy
#pragma unroll
    for (int i = 0; i < 11; i++) v[i] = 0.0f;

    for (int q = 0; q < qtot; q++) {
        // Keep the stream 2 chunks ahead (crosses batch boundaries)
        if (q + 2 < qtot) issue_chunk(q + 2);

        const int remaining = qtot - 1 - q;  // chunks issued after q
        if (remaining >= 2)      cp_wait<2>();
        else if (remaining == 1) cp_wait<1>();
        else                     cp_wait<0>();
        __syncwarp();

        const int bcur = gw + (q >> 3) * ws;
        if ((q & 7) == 0) {
            // New batch: load its means (broadcast)
            mx0 = mu_x[bcur * 3 + 0];
            mx1 = mu_x[bcur * 3 + 1];
            mx2 = mu_x[bcur * 3 + 2];
            my0 = mu_y[bcur * 3 + 0];
            my1 = mu_y[bcur * 3 + 1];
            my2 = mu_y[bcur * 3 + 2];
        }

        const float* fx = (const float*)(wbase + (q % 3) * SLOT_BYTES);
        const float* fy = fx + 384;  // +1536B

#pragma unroll
        for (int g = 0; g < 4; g++) {
            const int p = g * 32 + lane;
            const float u0 = fx[3 * p + 0] - mx0;
            const float u1 = fx[3 * p + 1] - mx1;
            const float u2 = fx[3 * p + 2] - mx2;
            const float w0 = fy[3 * p + 0] - my0;
            const float w1 = fy[3 * p + 1] - my1;
            const float w2 = fy[3 * p + 2] - my2;
            v[0] = fmaf(u0, w0, v[0]); v[1] = fmaf(u0, w1, v[1]); v[2] = fmaf(u0, w2, v[2]);
            v[3] = fmaf(u1, w0, v[3]); v[4] = fmaf(u1, w1, v[4]); v[5] = fmaf(u1, w2, v[5]);
            v[6] = fmaf(u2, w0, v[6]); v[7] = fmaf(u2, w1, v[7]); v[8] = fmaf(u2, w2, v[8]);
            v[9]  = fmaf(u0, u0, fmaf(u1, u1, fmaf(u2, u2, v[9])));
            v[10] = fmaf(w0, w0, fmaf(w1, w1, fmaf(w2, w2, v[10])));
        }
        __syncwarp();  // all lanes done reading slot before refill

        if ((q & 7) == 7) {
            // ---- Batch epilogue (next batch's loads already in flight) ----
#pragma unroll
            for (int off = 16; off > 0; off >>= 1) {
#pragma unroll
                for (int i = 0; i < 11; i++)
                    v[i] += __shfl_xor_sync(0xFFFFFFFFu, v[i], off);
            }

            float fro2 = 0.0f;
#pragma unroll
            for (int i = 0; i < 9; i++) fro2 = fmaf(v[i], v[i], fro2);
            const float invf = rsqrtf(fmaxf(fro2, 1e-30f));

            float X[9];
#pragma unroll
            for (int i = 0; i < 9; i++) X[i] = v[i] * invf;

#pragma unroll
            for (int it = 0; it < 8; it++) {
                float C[9];  // cofactors: X^{-T} = C / det
                C[0] = X[4] * X[8] - X[5] * X[7];
                C[1] = X[5] * X[6] - X[3] * X[8];
                C[2] = X[3] * X[7] - X[4] * X[6];
                C[3] = X[2] * X[7] - X[1] * X[8];
                C[4] = X[0] * X[8] - X[2] * X[6];
                C[5] = X[1] * X[6] - X[0] * X[7];
                C[6] = X[1] * X[5] - X[2] * X[4];
                C[7] = X[2] * X[3] - X[0] * X[5];
                C[8] = X[0] * X[4] - X[1] * X[3];
                float det = X[0] * C[0] + X[1] * C[1] + X[2] * C[2];
                float ad  = fmaxf(fabsf(det), 1e-30f);
                float eta = rcbrtf(ad);            // |det|^{-1/3}
                float k1  = 0.5f * eta;
                float k2  = 0.5f / (eta * det);    // keeps det's sign
#pragma unroll
                for (int i = 0; i < 9; i++) X[i] = k1 * X[i] + k2 * C[i];
            }

            const float t0 = my0 - (X[0] * mx0 + X[1] * mx1 + X[2] * mx2);
            const float t1 = my1 - (X[3] * mx0 + X[4] * mx1 + X[5] * mx2);
            const float t2 = my2 - (X[6] * mx0 + X[7] * mx1 + X[8] * mx2);
            const float sf = sqrtf(v[10]) / (sqrtf(v[9]) + 1e-6f);

            if (lane < 9) {
                float r = (lane == 0) ? X[0] :
                          (lane == 1) ? X[1] :
                          (lane == 2) ? X[2] :
                          (lane == 3) ? X[3] :
                          (lane == 4) ? X[4] :
                          (lane == 5) ? X[5] :
                          (lane == 6) ? X[6] :
                          (lane == 7) ? X[7] : X[8];
                out[(size_t)bcur * 9 + lane] = r;
            }
            if (lane < 3) {
                float tv = (lane == 0) ? t0 : (lane == 1) ? t1 : t2;
                out[(size_t)B * 9 + (size_t)bcur * 3 + lane] = tv;
            }
            if (lane == 0) {
                out[(size_t)B * 12 + bcur] = sf;
            }

            // Reset accumulators for the next batch
#pragma unroll
            for (int i = 0; i < 11; i++) v[i] = 0.0f;
        }
    }
}

extern "C" void kernel_launch(void* const* d_in, const int* in_sizes, int n_in,
                              void* d_out, int out_size)
{
    const float* x    = (const float*)d_in[0];
    const float* mu_x = (const float*)d_in[1];
    const float* y    = (const float*)d_in[2];
    const float* mu_y = (const float*)d_in[3];
    float* out        = (float*)d_out;

    const int B = in_sizes[1] / 3;  // mu_x is [B,3]

    cudaFuncSetAttribute(align9dof_kernel,
                         cudaFuncAttributeMaxDynamicSharedMemorySize, CTA_SMEM);

    int grid = 148 * 3;                       // persistent: 3 CTAs per SM
    const int maxg = (B + 7) / 8;
    if (grid > maxg) grid = maxg;

    align9dof_kernel<<<grid, 256, CTA_SMEM>>>(x, mu_x, y, mu_y, out, B);
}